// round 8
// baseline (speedup 1.0000x reference)
#include <cuda_runtime.h>
#include <cuda_bf16.h>
#include <cstdint>

#define BB 256
#define NN 512
#define DD 6
#define FF 128
#define MAXDEG 6
#define BN (BB * NN)
#define TM 128
#define SSTR 136      // smem row stride in bf16 (128 + 8 pad); 272B, 16B-multiple
#define NCH 64        // N chunk (output cols per phase)
#define SLOTS (BN + MAXDEG * TM)   // compact slot space upper bound

// ---- smem byte offsets ----
#define SM_SH   0                       // Sh: 128 x SSTR bf16 = 34816B
#define SM_SL   34816
#define SM_WH   69632                   // W chunk: 64 x SSTR bf16 = 17408B
#define SM_WL   87040
#define SM_NODE 104448                  // 128 ints
#define SM_BIAS 104960                  // 128 floats
#define SM_BYTES 105472

// ---- device scratch (allocation-free rule) ----
__device__ int g_list[MAXDEG * BN];
__device__ int g_cnt[MAXDEG];
__device__ int g_ps[MAXDEG + 1];                     // padded segment starts
__device__ int g_node[SLOTS];
__device__ __nv_bfloat16 g_sh[(size_t)SLOTS * FF];   // summed hi (bucket order)
__device__ __nv_bfloat16 g_sl[(size_t)SLOTS * FF];   // summed lo
__device__ __nv_bfloat16 g_wh[MAXDEG * FF * FF];     // W^T hi: [d][n][k]
__device__ __nv_bfloat16 g_wl[MAXDEG * FF * FF];     // W^T lo

__device__ __forceinline__ uint32_t smem_u32(const void* p) {
    uint32_t a;
    asm("{ .reg .u64 t; cvta.to.shared.u64 t, %1; cvt.u32.u64 %0, t; }" : "=r"(a) : "l"(p));
    return a;
}
__device__ __forceinline__ void cpa16(uint32_t dst, const void* src) {
    asm volatile("cp.async.cg.shared.global [%0], [%1], 16;" :: "r"(dst), "l"(src));
}
#define CPA_COMMIT() asm volatile("cp.async.commit_group;" ::: "memory")
#define CPA_WAIT0()  asm volatile("cp.async.wait_group 0;" ::: "memory")

__device__ __forceinline__ void ldm_x4(uint32_t& r0, uint32_t& r1, uint32_t& r2, uint32_t& r3,
                                       uint32_t addr) {
    asm volatile("ldmatrix.sync.aligned.m8n8.x4.shared.b16 {%0,%1,%2,%3}, [%4];"
                 : "=r"(r0), "=r"(r1), "=r"(r2), "=r"(r3) : "r"(addr));
}
__device__ __forceinline__ void mma16816(float* c, const uint32_t* a, uint32_t b0, uint32_t b1) {
    asm volatile("mma.sync.aligned.m16n8k16.row.col.f32.bf16.bf16.f32 "
                 "{%0,%1,%2,%3}, {%4,%5,%6,%7}, {%8,%9}, {%0,%1,%2,%3};"
                 : "+f"(c[0]), "+f"(c[1]), "+f"(c[2]), "+f"(c[3])
                 : "r"(a[0]), "r"(a[1]), "r"(a[2]), "r"(a[3]), "r"(b0), "r"(b1));
}

// ===================== kernel 0: zero counters =====================
__global__ void k_zero() {
    if (threadIdx.x < MAXDEG) g_cnt[threadIdx.x] = 0;
}

// ===================== kernel 1: bucket nodes by degree ============
__global__ void k_bucket(const int* __restrict__ edges) {
    __shared__ int c[MAXDEG];
    __shared__ int base[MAXDEG];
    int t = threadIdx.x;                    // 512 threads
    if (t < MAXDEG) c[t] = 0;
    __syncthreads();
    int node = blockIdx.x * 512 + t;
    int deg = 0;
#pragma unroll
    for (int s = 0; s < DD; s++) deg += (edges[node * DD + s] >= 0);
    if (deg >= MAXDEG) deg = MAXDEG - 1;
    int pos = atomicAdd(&c[deg], 1);
    __syncthreads();
    if (t < MAXDEG) base[t] = atomicAdd(&g_cnt[t], c[t]);
    __syncthreads();
    g_list[deg * BN + base[deg] + pos] = node;
}

// ===================== kernel 1b: padded prefix offsets ============
__global__ void k_prefix() {
    if (threadIdx.x == 0) {
        int off = 0;
#pragma unroll
        for (int d = 0; d < MAXDEG; d++) {
            g_ps[d] = off;
            off += (g_cnt[d] + TM - 1) & ~(TM - 1);
        }
        g_ps[MAXDEG] = off;
    }
}

// ===================== kernel 2: split+transpose W =================
__global__ void k_wsplit(const float* __restrict__ W) {
    int i = blockIdx.x * blockDim.x + threadIdx.x;   // < 6*128*128
    int d = i >> 14, rem = i & 16383, k = rem >> 7, n = rem & 127;
    float v = W[i];                                  // W[d][k][n]
    __nv_bfloat16 hi = __float2bfloat16(v);
    float lo = v - __bfloat162float(hi);
    int o = (d << 14) + (n << 7) + k;                // W^T[d][n][k]
    g_wh[o] = hi;
    g_wl[o] = __float2bfloat16(lo);
}

// ===================== kernel 3: gather+sum -> compact bf16 S ======
// one warp per compact slot; lane owns 4 floats (one float4)
__global__ __launch_bounds__(256)
void k_gather(const float* __restrict__ atoms, const int* __restrict__ edges) {
    int gw = (blockIdx.x * 256 + threadIdx.x) >> 5;
    int lane = threadIdx.x & 31;
    if (gw >= g_ps[MAXDEG]) return;
    int d = 0;
#pragma unroll
    for (int t = 1; t < MAXDEG; t++) if (gw >= g_ps[t]) d = t;
    int i = gw - g_ps[d];
    if (i >= g_cnt[d]) return;

    int node = g_list[d * BN + i];
    if (lane == 0) g_node[gw] = node;

    const float4* A = (const float4*)atoms;
    float4 acc = A[node * 32 + lane];
    int nb = (node >> 9) << 9;              // batch base (N=512)
    int eb = node * DD;
#pragma unroll
    for (int s = 0; s < DD; s++) {
        int e = edges[eb + s];
        if (e >= 0) {
            e = (e < NN) ? e : 0;
            float4 v = A[(nb + e) * 32 + lane];
            acc.x += v.x; acc.y += v.y; acc.z += v.z; acc.w += v.w;
        }
    }
    float vals[4] = {acc.x, acc.y, acc.z, acc.w};
    uint32_t hp[2], lp[2];
#pragma unroll
    for (int j = 0; j < 2; j++) {
        float v0 = vals[2 * j], v1 = vals[2 * j + 1];
        __nv_bfloat16 h0 = __float2bfloat16(v0);
        __nv_bfloat16 h1 = __float2bfloat16(v1);
        __nv_bfloat16 l0 = __float2bfloat16(v0 - __bfloat162float(h0));
        __nv_bfloat16 l1 = __float2bfloat16(v1 - __bfloat162float(h1));
        hp[j] = ((uint32_t)__bfloat16_as_ushort(h1) << 16) | __bfloat16_as_ushort(h0);
        lp[j] = ((uint32_t)__bfloat16_as_ushort(l1) << 16) | __bfloat16_as_ushort(l0);
    }
    ((uint2*)g_sh)[(size_t)gw * 32 + lane] = make_uint2(hp[0], hp[1]);
    ((uint2*)g_sl)[(size_t)gw * 32 + lane] = make_uint2(lp[0], lp[1]);
}

// ===================== kernel 4: HMMA GEMM over compact tiles ======
// grid (SLOTS/TM), 256 threads = 8 warps; warp w owns rows w*16..w*16+15
__global__ __launch_bounds__(256, 2)
void k_mma(const float* __restrict__ bias, float* __restrict__ out) {
    const int tileBase = blockIdx.x * TM;
    int d = 0;
#pragma unroll
    for (int t = 1; t < MAXDEG; t++) if (tileBase >= g_ps[t]) d = t;
    const int pe = g_ps[d] + g_cnt[d];      // valid end of this segment
    if (tileBase >= pe) return;

    extern __shared__ char smc[];
    const uint32_t sb = smem_u32(smc);
    const int tid = threadIdx.x;
    const int wid = tid >> 5;
    const int lid = tid & 31;

    int*   snode = (int*)(smc + SM_NODE);
    float* sbias = (float*)(smc + SM_BIAS);
    if (tid < TM) {
        snode[tid] = g_node[tileBase + tid];
        sbias[tid] = bias[d * FF + tid];
    }

    // ---- async stage: S tile (hi+lo) + W phase-0 chunk
    const char* shp = (const char*)g_sh + (size_t)tileBase * 256;
    const char* slp = (const char*)g_sl + (size_t)tileBase * 256;
    for (int i = tid; i < TM * 16; i += 256) {           // 16B chunks per row
        int row = i >> 4, ch = (i & 15) * 16;
        uint32_t dsto = (uint32_t)row * (SSTR * 2) + ch;
        cpa16(sb + SM_SH + dsto, shp + row * 256 + ch);
        cpa16(sb + SM_SL + dsto, slp + row * 256 + ch);
    }
    const char* whp = (const char*)(g_wh + (d << 14));
    const char* wlp = (const char*)(g_wl + (d << 14));
    for (int i = tid; i < NCH * 16; i += 256) {
        int row = i >> 4, ch = (i & 15) * 16;
        uint32_t dsto = (uint32_t)row * (SSTR * 2) + ch;
        cpa16(sb + SM_WH + dsto, whp + row * 256 + ch);
        cpa16(sb + SM_WL + dsto, wlp + row * 256 + ch);
    }
    CPA_COMMIT();
    CPA_WAIT0();
    __syncthreads();

    // ---- lane-invariant fragment addressing ----
    const int wrow = wid * 16;
    const int arow = wrow + (lid & 7) + ((lid >> 3) & 1) * 8;
    const int acol = ((lid >> 4) & 1) * 8;
    const uint32_t aoff = (uint32_t)(arow * SSTR + acol) * 2;
    const int bnl  = (lid & 7) + ((lid >> 4) & 1) * 8;
    const int bcol = ((lid >> 3) & 1) * 8;

    const int r0 = wrow + (lid >> 2);
    const int r1 = r0 + 8;
    const bool ok0 = (tileBase + r0) < pe;
    const bool ok1 = (tileBase + r1) < pe;
    float* op0 = out + (size_t)snode[r0] * FF;
    float* op1 = out + (size_t)snode[r1] * FF;
    const int cb = (lid & 3) * 2;

#pragma unroll
    for (int ph = 0; ph < 2; ph++) {
        if (ph == 1) {
            __syncthreads();               // all warps done with W chunk 0
            for (int i = tid; i < NCH * 16; i += 256) {
                int row = i >> 4, ch = (i & 15) * 16;
                uint32_t dsto = (uint32_t)row * (SSTR * 2) + ch;
                cpa16(sb + SM_WH + dsto, whp + (NCH + row) * 256 + ch);
                cpa16(sb + SM_WL + dsto, wlp + (NCH + row) * 256 + ch);
            }
            CPA_COMMIT();
            CPA_WAIT0();
            __syncthreads();
        }

        float acc[8][4];
#pragma unroll
        for (int t = 0; t < 8; t++)
#pragma unroll
            for (int q = 0; q < 4; q++) acc[t][q] = 0.f;

#pragma unroll
        for (int kb = 0; kb < 8; kb++) {
            const uint32_t kbyte = (uint32_t)kb * 32;   // 16 bf16
            uint32_t ah[4], al[4];
            ldm_x4(ah[0], ah[1], ah[2], ah[3], sb + SM_SH + aoff + kbyte);
            ldm_x4(al[0], al[1], al[2], al[3], sb + SM_SL + aoff + kbyte);
            uint32_t bh[4][4], bl[4][4];
#pragma unroll
            for (int p = 0; p < 4; p++) {
                uint32_t boff = (uint32_t)((p * 16 + bnl) * SSTR + bcol) * 2 + kbyte;
                ldm_x4(bh[p][0], bh[p][1], bh[p][2], bh[p][3], sb + SM_WH + boff);
                ldm_x4(bl[p][0], bl[p][1], bl[p][2], bl[p][3], sb + SM_WL + boff);
            }
#pragma unroll
            for (int p = 0; p < 4; p++) {
                mma16816(acc[2 * p],     ah, bh[p][0], bh[p][1]);
                mma16816(acc[2 * p + 1], ah, bh[p][2], bh[p][3]);
            }
#pragma unroll
            for (int p = 0; p < 4; p++) {
                mma16816(acc[2 * p],     ah, bl[p][0], bl[p][1]);
                mma16816(acc[2 * p + 1], ah, bl[p][2], bl[p][3]);
            }
#pragma unroll
            for (int p = 0; p < 4; p++) {
                mma16816(acc[2 * p],     al, bh[p][0], bh[p][1]);
                mma16816(acc[2 * p + 1], al, bh[p][2], bh[p][3]);
            }
        }

        const int cbase = ph * NCH;
#pragma unroll
        for (int t = 0; t < 8; t++) {
            int c = cbase + t * 8 + cb;
            float b0 = sbias[c], b1 = sbias[c + 1];
            if (ok0) {
                float x0 = fmaxf(acc[t][0] + b0, 0.f);
                float x1 = fmaxf(acc[t][1] + b1, 0.f);
                *(float2*)(op0 + c) = make_float2(x0, x1);
            }
            if (ok1) {
                float x2 = fmaxf(acc[t][2] + b0, 0.f);
                float x3 = fmaxf(acc[t][3] + b1, 0.f);
                *(float2*)(op1 + c) = make_float2(x2, x3);
            }
        }
    }
}

// ===================== launch =====================
extern "C" void kernel_launch(void* const* d_in, const int* in_sizes, int n_in,
                              void* d_out, int out_size) {
    const float* atoms = (const float*)d_in[0];
    const int*   edges = (const int*)d_in[1];
    const float* W     = (const float*)d_in[2];
    const float* bias  = (const float*)d_in[3];
    float*       out   = (float*)d_out;

    cudaFuncSetAttribute(k_mma, cudaFuncAttributeMaxDynamicSharedMemorySize, SM_BYTES);

    k_zero<<<1, 32>>>();
    k_bucket<<<BN / 512, 512>>>(edges);
    k_prefix<<<1, 32>>>();
    k_wsplit<<<(MAXDEG * FF * FF) / 256, 256>>>(W);
    k_gather<<<(SLOTS + 7) / 8, 256>>>(atoms, edges);
    k_mma<<<SLOTS / TM, 256, SM_BYTES>>>(bias, out);
}